// round 11
// baseline (speedup 1.0000x reference)
#include <cuda_runtime.h>
#include <math.h>
#include <stdint.h>

#define TT 4096
#define BB 32
#define KK 16
#define LMM 256
#define LD 32
#define HH 256
#define AA 16
#define NRW 512
#define NTB 131072
#define XW 192
#define G3 768

__device__ float g_xcat[(size_t)NTB * XW];
__device__ float g_gi[(size_t)NTB * G3];
__device__ float g_hid[(size_t)NTB * HH];
__device__ float g_logits[NTB * AA];
__device__ float g_dflag[NTB];
__device__ float g_mask[NTB];
__device__ int   g_dst[NTB];
__device__ int   g_cnt[NRW];
__device__ float g_Wc[XW * G3];
__device__ float g_bc[G3];
__device__ float g_klp[512];

__global__ void init_k() {
    int i = blockIdx.x * blockDim.x + threadIdx.x;
    if (i < NTB) { g_dflag[i] = 0.f; g_mask[i] = 0.f; }
    if (i < NRW) g_cnt[i] = 0;
}

__global__ void layout_k(const float* __restrict__ dones) {
    __shared__ float dch[256 * BB];
    int tid = threadIdx.x, b = tid;
    int ep = 0, start = 0; float prev = 0.f;
    for (int tc = 0; tc < TT; tc += 256) {
        for (int e = tid; e < 256 * BB; e += blockDim.x) dch[e] = dones[tc * BB + e];
        __syncthreads();
        if (b < BB) for (int u = 0; u < 256; ++u) {
            int t = tc + u;
            if (t > 0 && prev > 0.5f) { ep++; start = t; }
            int pos = t - start;
            float d = dch[u * BB + b]; prev = d;
            int di = -1;
            if (ep < KK && pos < LMM) {
                int row = b * KK + ep, slot = row * LMM + pos;
                di = slot; g_dflag[slot] = d; g_mask[slot] = 1.f; g_cnt[row]++;
            }
            g_dst[t * BB + b] = di;
        }
        __syncthreads();
    }
}

__global__ void prep_k(const float* __restrict__ Wsa, const float* __restrict__ bsa,
                       const float* __restrict__ Wi, const float* __restrict__ bi) {
    int idx = blockIdx.x * blockDim.x + threadIdx.x;
    if (idx >= 193 * G3) return;
    int a = idx / G3, j = idx % G3;
    const float* ar = (a < XW) ? (Wsa + a * HH) : bsa;
    float s = 0.f;
    for (int i = 0; i < HH; i++) s += ar[i] * Wi[i * G3 + j];
    if (a < XW) g_Wc[a * G3 + j] = s; else g_bc[j] = s + bi[j];
}

__device__ __forceinline__ void mlp_body(const float* X0, int ld0, int w0,
    const float* X1, int ld1, int w1, const float* W, const float* B,
    int OUT, int relu, float* Y, int ldy, const int* dmap) {
    __shared__ float xs[160 * 16];
    int n0 = blockIdx.x * 16, tid = threadIdx.x, IN = w0 + w1;
    for (int e = tid; e < 16 * IN; e += blockDim.x) {
        int r = e / IN, i = e % IN;
        xs[i * 16 + r] = (i < w0) ? X0[(size_t)(n0 + r) * ld0 + i]
                                  : X1[(size_t)(n0 + r) * ld1 + (i - w0)];
    }
    __syncthreads();
    int j = tid;
    float acc[16], bj = B[j];
#pragma unroll
    for (int r = 0; r < 16; r++) acc[r] = bj;
    for (int i = 0; i < IN; i++) {
        float w = W[i * OUT + j];
#pragma unroll
        for (int r = 0; r < 16; r++) acc[r] += xs[i * 16 + r] * w;
    }
#pragma unroll
    for (int r = 0; r < 16; r++) {
        float v = relu ? fmaxf(acc[r], 0.f) : acc[r];
        if (dmap) { int dn = dmap[n0 + r]; if (dn >= 0) Y[(size_t)dn * ldy + j] = v; }
        else Y[(size_t)(n0 + r) * ldy + j] = v;
    }
}

__global__ void se_k(const float* X, const float* W, const float* B) {
    mlp_body(X, 128, 128, 0, 0, 0, W, B, 128, 1, g_xcat, XW, 0);
}
__global__ void ce_k(const float* X, const float* W, const float* B) {
    mlp_body(X, 32, 32, 0, 0, 0, W, B, 64, 1, g_xcat + 128, XW, 0);
}
__global__ void hid_k(const float* MS, const float* W, const float* B) {
    mlp_body(g_xcat + 128, XW, 64, MS, 32, 32, W, B, 256, 0, g_hid, HH, g_dst);
}

__global__ void gemm_k() {
    __shared__ float As[64 * 96];
    __shared__ float Bs[96 * 64];
    int n0 = blockIdx.x * 64, j0 = blockIdx.y * 64, tid = threadIdx.x;
    int cg = tid & 15, rg = tid >> 4;
    float acc[4][4];
#pragma unroll
    for (int r = 0; r < 4; r++)
#pragma unroll
        for (int c = 0; c < 4; c++) acc[r][c] = 0.f;
    for (int kc = 0; kc < 192; kc += 96) {
        for (int e = tid; e < 64 * 96; e += 256) {
            int r = e / 96, c = e % 96;
            As[r * 96 + c] = g_xcat[(size_t)(n0 + r) * XW + kc + c];
        }
        for (int e = tid; e < 96 * 64; e += 256) {
            int k = e / 64, c = e % 64;
            Bs[k * 64 + c] = g_Wc[(kc + k) * G3 + j0 + c];
        }
        __syncthreads();
        const float* ap = As + rg * 4 * 96;
#pragma unroll 4
        for (int k = 0; k < 96; k++) {
            float4 b4 = *(const float4*)(Bs + k * 64 + cg * 4);
            float bv[4] = {b4.x, b4.y, b4.z, b4.w};
#pragma unroll
            for (int r = 0; r < 4; r++) {
                float a = ap[r * 96 + k];
#pragma unroll
                for (int c = 0; c < 4; c++) acc[r][c] += a * bv[c];
            }
        }
        __syncthreads();
    }
    float4 b4 = *(const float4*)(g_bc + j0 + cg * 4);
    float bb[4] = {b4.x, b4.y, b4.z, b4.w};
#pragma unroll
    for (int r = 0; r < 4; r++) {
        int dn = g_dst[n0 + rg * 4 + r];
        if (dn >= 0) {
            float4 o = make_float4(acc[r][0] + bb[0], acc[r][1] + bb[1],
                                   acc[r][2] + bb[2], acc[r][3] + bb[3]);
            *(float4*)(g_gi + (size_t)dn * G3 + j0 + cg * 4) = o;
        }
    }
}

__global__ void kl_k(const float* __restrict__ lm, const float* __restrict__ lv,
                     const float* __restrict__ lmt, const float* __restrict__ lvt) {
    __shared__ float red[256];
    int n = blockIdx.x * 256 + threadIdx.x;
    int t = n >> 5;
    int st = n * LD;
    float s = 0.f;
    const float* ms[2] = {lm, lmt};
    const float* vs[2] = {lv, lvt};
#pragma unroll
    for (int g = 0; g < 2; g++)
        for (int d = 0; d < LD; d++) {
            float mu = ms[g][st + d], logE = vs[g][st + d];
            float m = 0.f, logS = 0.f;
            if (t > 0) { m = ms[g][st - BB * LD + d]; logS = vs[g][st - BB * LD + d]; }
            float dd = m - mu;
            s += logS - logE + expf(logE - logS) + dd * dd * expf(-logS);
        }
    red[threadIdx.x] = 0.5f * (s - 64.f);
    __syncthreads();
    for (int o = 128; o; o >>= 1) {
        if (threadIdx.x < o) red[threadIdx.x] += red[threadIdx.x + o];
        __syncthreads();
    }
    if (threadIdx.x == 0) g_klp[blockIdx.x] = red[0];
}

__global__ void klf_k(float* out) {
    __shared__ float red[512];
    red[threadIdx.x] = g_klp[threadIdx.x];
    __syncthreads();
    for (int o = 256; o; o >>= 1) {
        if (threadIdx.x < o) red[threadIdx.x] += red[threadIdx.x + o];
        __syncthreads();
    }
    if (threadIdx.x == 0) out[0] = red[0];
}

__global__ void __launch_bounds__(256, 1)
recur_k(const float* __restrict__ Whg, const float* __restrict__ bh_,
        const float* __restrict__ Wout, const float* __restrict__ bout) {
    extern __shared__ float sm[];
    float* whs = sm;                 /* 64*768  */
    float* hs  = sm + 64 * G3;       /* 256*4   */
    float* wos = hs + 1024;          /* 256*16  */
    float* bos = wos + 4096;         /* 16      */
    int t = threadIdx.x, row0 = blockIdx.x * 4;
    for (int e = t; e < 64 * G3; e += 256) whs[e] = Whg[e];
    for (int e = t; e < 256 * 16; e += 256) wos[e] = Wout[e];
    if (t < 16) bos[t] = bout[t];
    float bh0 = bh_[t], bh1 = bh_[t + 256], bh2 = bh_[t + 512];
#pragma unroll
    for (int r = 0; r < 4; r++)
        hs[t * 4 + r] = g_hid[(size_t)(row0 + r) * LMM * HH + t];
    __syncthreads();
    int lr = t >> 6, sub = t & 63, la = sub >> 2, lq = sub & 3;

    for (int p = 0; p < LMM; p++) {
#pragma unroll
        for (int r = 0; r < 4; r++) {
            int slot = (row0 + r) * LMM + p;
            if (g_dflag[slot] > 0.5f) hs[t * 4 + r] = g_hid[(size_t)slot * HH + t];
        }
        __syncthreads();
        float gi0[4], gi1[4], gi2[4];
#pragma unroll
        for (int r = 0; r < 4; r++) {
            const float* gp = g_gi + (size_t)((row0 + r) * LMM + p) * G3 + t;
            gi0[r] = gp[0]; gi1[r] = gp[256]; gi2[r] = gp[512];
        }
        float aR[4] = {0, 0, 0, 0}, aZ[4] = {0, 0, 0, 0}, aN[4] = {0, 0, 0, 0};
        const float4* h4 = (const float4*)hs;
#pragma unroll 4
        for (int i = 0; i < 256; i++) {
            const float* wp = (i < 64) ? (whs + i * G3 + t) : (Whg + i * G3 + t);
            float w0 = wp[0], w1 = wp[256], w2 = wp[512];
            float4 hv = h4[i];
            aR[0] += hv.x * w0; aR[1] += hv.y * w0; aR[2] += hv.z * w0; aR[3] += hv.w * w0;
            aZ[0] += hv.x * w1; aZ[1] += hv.y * w1; aZ[2] += hv.z * w1; aZ[3] += hv.w * w1;
            aN[0] += hv.x * w2; aN[1] += hv.y * w2; aN[2] += hv.z * w2; aN[3] += hv.w * w2;
        }
        __syncthreads();
#pragma unroll
        for (int r = 0; r < 4; r++) {
            float rg = 1.f / (1.f + expf(-(gi0[r] + aR[r] + bh0)));
            float zg = 1.f / (1.f + expf(-(gi1[r] + aZ[r] + bh1)));
            float ng = tanhf(gi2[r] + rg * (aN[r] + bh2));
            hs[t * 4 + r] = (1.f - zg) * ng + zg * hs[t * 4 + r];
        }
        __syncthreads();
        float part = 0.f;
#pragma unroll 8
        for (int i = 0; i < 64; i++) {
            int j = lq * 64 + i;
            part += hs[j * 4 + lr] * wos[j * 16 + la];
        }
        part += __shfl_xor_sync(0xffffffffu, part, 1);
        part += __shfl_xor_sync(0xffffffffu, part, 2);
        if (lq == 0) {
            int slot = (row0 + lr) * LMM + p;
            g_logits[slot * AA + la] = (part + bos[la]) * g_mask[slot];
        }
        __syncthreads();
    }
}

__global__ void out_k(const int* __restrict__ pact, float* __restrict__ dout) {
    int l = blockIdx.x, b = threadIdx.x;
    float acc[16];
#pragma unroll
    for (int a = 0; a < 16; a++) acc[a] = 0.f;
    for (int k = 0; k < KK; k++) {
        int row = b * KK + k;
        int pp = l - (LMM - g_cnt[row]);
        if (pp >= 0) {
            const float* lp = g_logits + (row * LMM + pp) * AA;
#pragma unroll
            for (int a = 0; a < 16; a++) acc[a] += lp[a];
        }
    }
    float mx = acc[0];
#pragma unroll
    for (int a = 1; a < 16; a++) mx = fmaxf(mx, acc[a]);
    float se = 0.f;
#pragma unroll
    for (int a = 0; a < 16; a++) se += expf(acc[a] - mx);
    float lse = logf(se) + mx;
    int act = pact[l * BB + b];
    float lpv = acc[act] - lse;
    for (int o = 16; o; o >>= 1) lpv += __shfl_down_sync(0xffffffffu, lpv, o);
    if (b == 0) dout[1 + l] = lpv;
}

extern "C" void kernel_launch(void* const* d_in, const int* in_sizes, int n_in,
                              void* d_out, int out_size) {
    const float* state = (const float*)d_in[0];
    const float* lmean = (const float*)d_in[1];
    const float* llogv = (const float*)d_in[2];
    const float* lmeant = (const float*)d_in[3];
    const float* llogvt = (const float*)d_in[4];
    const float* achar = (const float*)d_in[5];
    const float* mstate = (const float*)d_in[6];
    const int*   pact   = (const int*)d_in[7];
    const float* dones  = (const float*)d_in[8];
    const float* Wse = (const float*)d_in[9];
    const float* bse = (const float*)d_in[10];
    const float* Wce = (const float*)d_in[11];
    const float* bce = (const float*)d_in[12];
    const float* Wsa = (const float*)d_in[13];
    const float* bsa = (const float*)d_in[14];
    const float* Wh  = (const float*)d_in[15];
    const float* bh  = (const float*)d_in[16];
    const float* Wi  = (const float*)d_in[17];
    const float* bi  = (const float*)d_in[18];
    const float* Whh = (const float*)d_in[19];
    const float* bhh = (const float*)d_in[20];
    const float* Wout = (const float*)d_in[21];
    const float* bout = (const float*)d_in[22];
    float* dout = (float*)d_out;

    static int attr_done = 0;
    size_t rsm = (size_t)(64 * G3 + 1024 + 4096 + 16) * sizeof(float);
    if (!attr_done) {
        cudaFuncSetAttribute(recur_k, cudaFuncAttributeMaxDynamicSharedMemorySize, (int)rsm);
        attr_done = 1;
    }

    init_k<<<(NTB + 255) / 256, 256>>>();
    layout_k<<<1, 256>>>(dones);
    prep_k<<<(193 * G3 + 255) / 256, 256>>>(Wsa, bsa, Wi, bi);
    se_k<<<NTB / 16, 128>>>(state, Wse, bse);
    ce_k<<<NTB / 16, 64>>>(achar, Wce, bce);
    hid_k<<<NTB / 16, 256>>>(mstate, Wh, bh);
    gemm_k<<<dim3(NTB / 64, G3 / 64), 256>>>();
    kl_k<<<512, 256>>>(lmean, llogv, lmeant, llogvt);
    klf_k<<<1, 512>>>(dout);
    recur_k<<<128, 256, rsm>>>(Whh, bhh, Wout, bout);
    out_k<<<LMM, 32>>>(pact, dout);
}

// round 13
// speedup vs baseline: 1.0727x; 1.0727x over previous
#include <cuda_runtime.h>
#include <math.h>
#include <stdint.h>

#define TT 4096
#define BB 32
#define KK 16
#define LMM 256
#define LD 32
#define HH 256
#define AA 16
#define NRW 512
#define NTB 131072
#define XW 192
#define G3 768

typedef unsigned long long u64;

__device__ float g_xcat[(size_t)NTB * XW];
__device__ float g_gi[(size_t)NTB * G3];
__device__ float g_hid[(size_t)NTB * HH];
__device__ float g_logits[NTB * AA];
__device__ float g_dflag[NTB];
__device__ float g_mask[NTB];
__device__ int   g_dst[NTB];
__device__ int   g_cnt[NRW];
__device__ float g_Wc[XW * G3];
__device__ float g_bc[G3];
__device__ float g_klp[512];

/* ---- packed dual-fp32 helpers (sm_100+) ---- */
__device__ __forceinline__ u64 ffma2(u64 a, u64 b, u64 c) {
    u64 d; asm("fma.rn.f32x2 %0, %1, %2, %3;" : "=l"(d) : "l"(a), "l"(b), "l"(c)); return d;
}
__device__ __forceinline__ u64 splat2(float x) {
    u64 d; asm("mov.b64 %0, {%1, %1};" : "=l"(d) : "f"(x)); return d;
}
__device__ __forceinline__ u64 pack2(float lo, float hi) {
    u64 d; asm("mov.b64 %0, {%1, %2};" : "=l"(d) : "f"(lo), "f"(hi)); return d;
}
__device__ __forceinline__ float2 unpack2(u64 v) {
    float2 r; asm("mov.b64 {%0, %1}, %2;" : "=f"(r.x), "=f"(r.y) : "l"(v)); return r;
}

__global__ void init_k() {
    int i = blockIdx.x * blockDim.x + threadIdx.x;
    if (i < NTB) { g_dflag[i] = 0.f; g_mask[i] = 0.f; }
    if (i < NRW) g_cnt[i] = 0;
}

__global__ void layout_k(const float* __restrict__ dones) {
    __shared__ float dch[256 * BB];
    int tid = threadIdx.x, b = tid;
    int ep = 0, start = 0; float prev = 0.f;
    for (int tc = 0; tc < TT; tc += 256) {
        for (int e = tid; e < 256 * BB; e += blockDim.x) dch[e] = dones[tc * BB + e];
        __syncthreads();
        if (b < BB) for (int u = 0; u < 256; ++u) {
            int t = tc + u;
            if (t > 0 && prev > 0.5f) { ep++; start = t; }
            int pos = t - start;
            float d = dch[u * BB + b]; prev = d;
            int di = -1;
            if (ep < KK && pos < LMM) {
                int row = b * KK + ep, slot = row * LMM + pos;
                di = slot; g_dflag[slot] = d; g_mask[slot] = 1.f; g_cnt[row]++;
            }
            g_dst[t * BB + b] = di;
        }
        __syncthreads();
    }
}

__global__ void prep_k(const float* __restrict__ Wsa, const float* __restrict__ bsa,
                       const float* __restrict__ Wi, const float* __restrict__ bi) {
    int idx = blockIdx.x * blockDim.x + threadIdx.x;
    if (idx >= 193 * G3) return;
    int a = idx / G3, j = idx % G3;
    const float* ar = (a < XW) ? (Wsa + a * HH) : bsa;
    float s = 0.f;
    for (int i = 0; i < HH; i++) s += ar[i] * Wi[i * G3 + j];
    if (a < XW) g_Wc[a * G3 + j] = s; else g_bc[j] = s + bi[j];
}

/* ---- MLPs: 16 rows per block, thread = output col, f32x2 row-pair accum ---- */
__device__ __forceinline__ void mlp_body(const float* X0, int ld0, int w0,
    const float* X1, int ld1, int w1, const float* W, const float* B,
    int OUT, int relu, float* Y, int ldy, const int* dmap) {
    __shared__ __align__(16) float xs[160 * 16];
    int n0 = blockIdx.x * 16, tid = threadIdx.x, IN = w0 + w1;
    for (int e = tid; e < 16 * IN; e += blockDim.x) {
        int r = e / IN, i = e % IN;
        xs[i * 16 + r] = (i < w0) ? X0[(size_t)(n0 + r) * ld0 + i]
                                  : X1[(size_t)(n0 + r) * ld1 + (i - w0)];
    }
    __syncthreads();
    const ulonglong2* X64 = (const ulonglong2*)xs;
    int j = tid;
    u64 accP[8];
    u64 bs = splat2(B[j]);
#pragma unroll
    for (int k = 0; k < 8; k++) accP[k] = bs;
    for (int i = 0; i < IN; i++) {
        ulonglong2 x0 = X64[i * 4 + 0], x1 = X64[i * 4 + 1];
        ulonglong2 x2 = X64[i * 4 + 2], x3 = X64[i * 4 + 3];
        u64 ws = splat2(W[i * OUT + j]);
        accP[0] = ffma2(x0.x, ws, accP[0]); accP[1] = ffma2(x0.y, ws, accP[1]);
        accP[2] = ffma2(x1.x, ws, accP[2]); accP[3] = ffma2(x1.y, ws, accP[3]);
        accP[4] = ffma2(x2.x, ws, accP[4]); accP[5] = ffma2(x2.y, ws, accP[5]);
        accP[6] = ffma2(x3.x, ws, accP[6]); accP[7] = ffma2(x3.y, ws, accP[7]);
    }
#pragma unroll
    for (int k = 0; k < 8; k++) {
        float2 v = unpack2(accP[k]);
        float va = relu ? fmaxf(v.x, 0.f) : v.x;
        float vb = relu ? fmaxf(v.y, 0.f) : v.y;
        int ra = 2 * k, rb = 2 * k + 1;
        if (dmap) {
            int da = dmap[n0 + ra]; if (da >= 0) Y[(size_t)da * ldy + j] = va;
            int db = dmap[n0 + rb]; if (db >= 0) Y[(size_t)db * ldy + j] = vb;
        } else {
            Y[(size_t)(n0 + ra) * ldy + j] = va;
            Y[(size_t)(n0 + rb) * ldy + j] = vb;
        }
    }
}

__global__ void se_k(const float* X, const float* W, const float* B) {
    mlp_body(X, 128, 128, 0, 0, 0, W, B, 128, 1, g_xcat, XW, 0);
}
__global__ void ce_k(const float* X, const float* W, const float* B) {
    mlp_body(X, 32, 32, 0, 0, 0, W, B, 64, 1, g_xcat + 128, XW, 0);
}
__global__ void hid_k(const float* MS, const float* W, const float* B) {
    mlp_body(g_xcat + 128, XW, 64, MS, 32, 32, W, B, 256, 0, g_hid, HH, g_dst);
}

/* ---- gi GEMM 64x64 tiles, f32x2 col-pair accum ---- */
__global__ void gemm_k() {
    __shared__ __align__(16) float As[64 * 96];
    __shared__ __align__(16) float Bs[96 * 64];
    int n0 = blockIdx.x * 64, j0 = blockIdx.y * 64, tid = threadIdx.x;
    int cg = tid & 15, rg = tid >> 4;
    u64 accP[4][2];
#pragma unroll
    for (int r = 0; r < 4; r++) { accP[r][0] = 0ull; accP[r][1] = 0ull; }
    const float4* Xc4 = (const float4*)g_xcat;
    const float4* Wc4 = (const float4*)g_Wc;
    for (int kc = 0; kc < 192; kc += 96) {
        float4* As4 = (float4*)As;
        for (int e = tid; e < 64 * 24; e += 256) {
            int r = e / 24, c4 = e % 24;
            As4[e] = Xc4[(size_t)(n0 + r) * 48 + kc / 4 + c4];
        }
        float4* Bs4 = (float4*)Bs;
        for (int e = tid; e < 96 * 16; e += 256) {
            int k = e / 16, c4 = e % 16;
            Bs4[e] = Wc4[(size_t)(kc + k) * 192 + j0 / 4 + c4];
        }
        __syncthreads();
        const float4* A4 = ((const float4*)As) + rg * 96;
        const ulonglong2* B64 = (const ulonglong2*)Bs;
#pragma unroll 2
        for (int k4 = 0; k4 < 24; k4++) {
            float4 a0 = A4[k4], a1 = A4[24 + k4], a2 = A4[48 + k4], a3 = A4[72 + k4];
            float av[4][4] = {{a0.x, a0.y, a0.z, a0.w}, {a1.x, a1.y, a1.z, a1.w},
                              {a2.x, a2.y, a2.z, a2.w}, {a3.x, a3.y, a3.z, a3.w}};
#pragma unroll
            for (int kk = 0; kk < 4; kk++) {
                ulonglong2 b2 = B64[(k4 * 4 + kk) * 16 + cg];
#pragma unroll
                for (int r = 0; r < 4; r++) {
                    u64 ws = splat2(av[r][kk]);
                    accP[r][0] = ffma2(ws, b2.x, accP[r][0]);
                    accP[r][1] = ffma2(ws, b2.y, accP[r][1]);
                }
            }
        }
        __syncthreads();
    }
    float4 b4 = *(const float4*)(g_bc + j0 + cg * 4);
#pragma unroll
    for (int r = 0; r < 4; r++) {
        int dn = g_dst[n0 + rg * 4 + r];
        if (dn >= 0) {
            float2 v0 = unpack2(accP[r][0]), v1 = unpack2(accP[r][1]);
            float4 o = make_float4(v0.x + b4.x, v0.y + b4.y, v1.x + b4.z, v1.y + b4.w);
            *(float4*)(g_gi + (size_t)dn * G3 + j0 + cg * 4) = o;
        }
    }
}

__global__ void kl_k(const float* __restrict__ lm, const float* __restrict__ lv,
                     const float* __restrict__ lmt, const float* __restrict__ lvt) {
    __shared__ float red[256];
    int n = blockIdx.x * 256 + threadIdx.x;
    int t = n >> 5;
    int st = n * LD;
    float s = 0.f;
    const float* ms[2] = {lm, lmt};
    const float* vs[2] = {lv, lvt};
#pragma unroll
    for (int g = 0; g < 2; g++)
        for (int d = 0; d < LD; d++) {
            float mu = ms[g][st + d], logE = vs[g][st + d];
            float m = 0.f, logS = 0.f;
            if (t > 0) { m = ms[g][st - BB * LD + d]; logS = vs[g][st - BB * LD + d]; }
            float dd = m - mu;
            s += logS - logE + expf(logE - logS) + dd * dd * expf(-logS);
        }
    red[threadIdx.x] = 0.5f * (s - 64.f);
    __syncthreads();
    for (int o = 128; o; o >>= 1) {
        if (threadIdx.x < o) red[threadIdx.x] += red[threadIdx.x + o];
        __syncthreads();
    }
    if (threadIdx.x == 0) g_klp[blockIdx.x] = red[0];
}

__global__ void klf_k(float* out) {
    __shared__ float red[512];
    red[threadIdx.x] = g_klp[threadIdx.x];
    __syncthreads();
    for (int o = 256; o; o >>= 1) {
        if (threadIdx.x < o) red[threadIdx.x] += red[threadIdx.x + o];
        __syncthreads();
    }
    if (threadIdx.x == 0) out[0] = red[0];
}

/* ---- GRU recurrence: 128 blocks x 4 rows, split LDS/LDG weight loops, f32x2 ---- */
__global__ void __launch_bounds__(256, 1)
recur_k(const float* __restrict__ Whg, const float* __restrict__ bh_,
        const float* __restrict__ Wout, const float* __restrict__ bout) {
    extern __shared__ float sm[];
    float* whs = sm;                                /* 64*768 floats          */
    u64* hsA = (u64*)(sm + 64 * G3);                /* 256 pairs (rows 0,1)   */
    u64* hsB = hsA + 256;                           /* 256 pairs (rows 2,3)   */
    float* wos = (float*)(hsB + 256);               /* 256*16                 */
    float* bos = wos + 4096;                        /* 16                     */
    int t = threadIdx.x, row0 = blockIdx.x * 4;
    {
        float4* d = (float4*)whs; const float4* s = (const float4*)Whg;
        for (int e = t; e < 64 * G3 / 4; e += 256) d[e] = s[e];
        float4* d2 = (float4*)wos; const float4* s2 = (const float4*)Wout;
        for (int e = t; e < 1024; e += 256) d2[e] = s2[e];
        if (t < 16) bos[t] = bout[t];
    }
    float bh0 = bh_[t], bh1 = bh_[t + 256], bh2 = bh_[t + 512];
    float h0 = g_hid[(size_t)(row0 + 0) * LMM * HH + t];
    float h1 = g_hid[(size_t)(row0 + 1) * LMM * HH + t];
    float h2 = g_hid[(size_t)(row0 + 2) * LMM * HH + t];
    float h3 = g_hid[(size_t)(row0 + 3) * LMM * HH + t];
    hsA[t] = pack2(h0, h1); hsB[t] = pack2(h2, h3);
    int lr = t >> 6, sub = t & 63, la = sub >> 2, lq = sub & 3;
    const float* losrc = (lr < 2) ? (const float*)hsA : (const float*)hsB;
    int loff = lr & 1;
    __syncthreads();

    for (int p = 0; p < LMM; p++) {
        /* reset h <- hid where done */
        int s0 = (row0 + 0) * LMM + p, s1 = s0 + LMM, s2 = s1 + LMM, s3 = s2 + LMM;
        if (g_dflag[s0] > 0.5f) h0 = g_hid[(size_t)s0 * HH + t];
        if (g_dflag[s1] > 0.5f) h1 = g_hid[(size_t)s1 * HH + t];
        if (g_dflag[s2] > 0.5f) h2 = g_hid[(size_t)s2 * HH + t];
        if (g_dflag[s3] > 0.5f) h3 = g_hid[(size_t)s3 * HH + t];
        hsA[t] = pack2(h0, h1); hsB[t] = pack2(h2, h3);
        __syncthreads();

        const float* gp0 = g_gi + (size_t)s0 * G3 + t;
        const float* gp1 = g_gi + (size_t)s1 * G3 + t;
        const float* gp2 = g_gi + (size_t)s2 * G3 + t;
        const float* gp3 = g_gi + (size_t)s3 * G3 + t;
        float gi00 = gp0[0], gi01 = gp0[256], gi02 = gp0[512];
        float gi10 = gp1[0], gi11 = gp1[256], gi12 = gp1[512];
        float gi20 = gp2[0], gi21 = gp2[256], gi22 = gp2[512];
        float gi30 = gp3[0], gi31 = gp3[256], gi32 = gp3[512];

        u64 aR0 = 0ull, aR1 = 0ull, aZ0 = 0ull, aZ1 = 0ull, aN0 = 0ull, aN1 = 0ull;
#pragma unroll 4
        for (int i = 0; i < 64; i++) {
            const float* wp = whs + i * G3 + t;
            u64 hA = hsA[i], hB = hsB[i];
            u64 w0 = splat2(wp[0]), w1 = splat2(wp[256]), w2 = splat2(wp[512]);
            aR0 = ffma2(hA, w0, aR0); aR1 = ffma2(hB, w0, aR1);
            aZ0 = ffma2(hA, w1, aZ0); aZ1 = ffma2(hB, w1, aZ1);
            aN0 = ffma2(hA, w2, aN0); aN1 = ffma2(hB, w2, aN1);
        }
#pragma unroll 4
        for (int i = 64; i < 256; i++) {
            const float* wp = Whg + i * G3 + t;
            u64 hA = hsA[i], hB = hsB[i];
            u64 w0 = splat2(wp[0]), w1 = splat2(wp[256]), w2 = splat2(wp[512]);
            aR0 = ffma2(hA, w0, aR0); aR1 = ffma2(hB, w0, aR1);
            aZ0 = ffma2(hA, w1, aZ0); aZ1 = ffma2(hB, w1, aZ1);
            aN0 = ffma2(hA, w2, aN0); aN1 = ffma2(hB, w2, aN1);
        }
        __syncthreads();

        float2 rA = unpack2(aR0), rB = unpack2(aR1);
        float2 zA = unpack2(aZ0), zB = unpack2(aZ1);
        float2 nA = unpack2(aN0), nB = unpack2(aN1);
        {
            float rg = 1.f / (1.f + expf(-(gi00 + rA.x + bh0)));
            float zg = 1.f / (1.f + expf(-(gi01 + zA.x + bh1)));
            float ng = tanhf(gi02 + rg * (nA.x + bh2));
            h0 = (1.f - zg) * ng + zg * h0;
        }
        {
            float rg = 1.f / (1.f + expf(-(gi10 + rA.y + bh0)));
            float zg = 1.f / (1.f + expf(-(gi11 + zA.y + bh1)));
            float ng = tanhf(gi12 + rg * (nA.y + bh2));
            h1 = (1.f - zg) * ng + zg * h1;
        }
        {
            float rg = 1.f / (1.f + expf(-(gi20 + rB.x + bh0)));
            float zg = 1.f / (1.f + expf(-(gi21 + zB.x + bh1)));
            float ng = tanhf(gi22 + rg * (nB.x + bh2));
            h2 = (1.f - zg) * ng + zg * h2;
        }
        {
            float rg = 1.f / (1.f + expf(-(gi30 + rB.y + bh0)));
            float zg = 1.f / (1.f + expf(-(gi31 + zB.y + bh1)));
            float ng = tanhf(gi32 + rg * (nB.y + bh2));
            h3 = (1.f - zg) * ng + zg * h3;
        }
        hsA[t] = pack2(h0, h1); hsB[t] = pack2(h2, h3);
        __syncthreads();

        float part = 0.f;
#pragma unroll 8
        for (int i = 0; i < 64; i++) {
            int j = lq * 64 + i;
            part += losrc[j * 2 + loff] * wos[j * 16 + la];
        }
        part += __shfl_xor_sync(0xffffffffu, part, 1);
        part += __shfl_xor_sync(0xffffffffu, part, 2);
        if (lq == 0) {
            int slot = (row0 + lr) * LMM + p;
            g_logits[slot * AA + la] = (part + bos[la]) * g_mask[slot];
        }
        __syncthreads();
    }
}

__global__ void out_k(const int* __restrict__ pact, float* __restrict__ dout) {
    int l = blockIdx.x, b = threadIdx.x;
    float acc[16];
#pragma unroll
    for (int a = 0; a < 16; a++) acc[a] = 0.f;
    for (int k = 0; k < KK; k++) {
        int row = b * KK + k;
        int pp = l - (LMM - g_cnt[row]);
        if (pp >= 0) {
            const float* lp = g_logits + (row * LMM + pp) * AA;
#pragma unroll
            for (int a = 0; a < 16; a++) acc[a] += lp[a];
        }
    }
    float mx = acc[0];
#pragma unroll
    for (int a = 1; a < 16; a++) mx = fmaxf(mx, acc[a]);
    float se = 0.f;
#pragma unroll
    for (int a = 0; a < 16; a++) se += expf(acc[a] - mx);
    float lse = logf(se) + mx;
    int act = pact[l * BB + b];
    float lpv = acc[act] - lse;
    for (int o = 16; o; o >>= 1) lpv += __shfl_down_sync(0xffffffffu, lpv, o);
    if (b == 0) dout[1 + l] = lpv;
}

extern "C" void kernel_launch(void* const* d_in, const int* in_sizes, int n_in,
                              void* d_out, int out_size) {
    const float* state = (const float*)d_in[0];
    const float* lmean = (const float*)d_in[1];
    const float* llogv = (const float*)d_in[2];
    const float* lmeant = (const float*)d_in[3];
    const float* llogvt = (const float*)d_in[4];
    const float* achar = (const float*)d_in[5];
    const float* mstate = (const float*)d_in[6];
    const int*   pact   = (const int*)d_in[7];
    const float* dones  = (const float*)d_in[8];
    const float* Wse = (const float*)d_in[9];
    const float* bse = (const float*)d_in[10];
    const float* Wce = (const float*)d_in[11];
    const float* bce = (const float*)d_in[12];
    const float* Wsa = (const float*)d_in[13];
    const float* bsa = (const float*)d_in[14];
    const float* Wh  = (const float*)d_in[15];
    const float* bh  = (const float*)d_in[16];
    const float* Wi  = (const float*)d_in[17];
    const float* bi  = (const float*)d_in[18];
    const float* Whh = (const float*)d_in[19];
    const float* bhh = (const float*)d_in[20];
    const float* Wout = (const float*)d_in[21];
    const float* bout = (const float*)d_in[22];
    float* dout = (float*)d_out;

    static int attr_done = 0;
    size_t rsm = (size_t)(64 * G3) * 4 + 512 * 8 + 4096 * 4 + 64;
    if (!attr_done) {
        cudaFuncSetAttribute(recur_k, cudaFuncAttributeMaxDynamicSharedMemorySize, (int)rsm);
        attr_done = 1;
    }

    init_k<<<(NTB + 255) / 256, 256>>>();
    layout_k<<<1, 256>>>(dones);
    prep_k<<<(193 * G3 + 255) / 256, 256>>>(Wsa, bsa, Wi, bi);
    se_k<<<NTB / 16, 128>>>(state, Wse, bse);
    ce_k<<<NTB / 16, 64>>>(achar, Wce, bce);
    hid_k<<<NTB / 16, 256>>>(mstate, Wh, bh);
    gemm_k<<<dim3(NTB / 64, G3 / 64), 256>>>();
    kl_k<<<512, 256>>>(lmean, llogv, lmeant, llogvt);
    klf_k<<<1, 512>>>(dout);
    recur_k<<<128, 256, rsm>>>(Whh, bhh, Wout, bout);
    out_k<<<LMM, 32>>>(pact, dout);
}

// round 15
// speedup vs baseline: 1.4754x; 1.3754x over previous
#include <cuda_runtime.h>
#include <math.h>
#include <stdint.h>

#define TT 4096
#define BB 32
#define KK 16
#define LMM 256
#define LD 32
#define HH 256
#define AA 16
#define NRW 512
#define NTB 131072
#define XW 192
#define G3 768

typedef unsigned long long u64;

__device__ float g_xcat[(size_t)NTB * XW];
__device__ float g_gi[(size_t)NTB * G3];
__device__ float g_hid[(size_t)NTB * HH];
__device__ float g_logits[NTB * AA];
__device__ float g_dflag[NTB];
__device__ float g_mask[NTB];
__device__ int   g_dst[NTB];
__device__ int   g_cnt[NRW];
__device__ float g_Wc[XW * G3];
__device__ float g_bc[G3];
__device__ float4 g_Wh4[64 * G3];   /* [i/4][col] packed 4 consecutive rows */
__device__ float g_klp[512];

__device__ __forceinline__ u64 ffma2(u64 a, u64 b, u64 c) {
    u64 d; asm("fma.rn.f32x2 %0, %1, %2, %3;" : "=l"(d) : "l"(a), "l"(b), "l"(c)); return d;
}
__device__ __forceinline__ u64 splat2(float x) {
    u64 d; asm("mov.b64 %0, {%1, %1};" : "=l"(d) : "f"(x)); return d;
}
__device__ __forceinline__ float2 unpack2(u64 v) {
    float2 r; asm("mov.b64 {%0, %1}, %2;" : "=f"(r.x), "=f"(r.y) : "l"(v)); return r;
}

/* ---- launch 0: zero scratch + episode layout (single block) ---- */
__global__ void layoutinit_k(const float* __restrict__ dones) {
    __shared__ float dch[256 * BB];
    int tid = threadIdx.x;
    for (int e = tid; e < NTB; e += 256) { g_dflag[e] = 0.f; g_mask[e] = 0.f; }
    for (int e = tid; e < NRW; e += 256) g_cnt[e] = 0;
    __syncthreads();
    int b = tid;
    int ep = 0, start = 0; float prev = 0.f;
    for (int tc = 0; tc < TT; tc += 256) {
        for (int e = tid; e < 256 * BB; e += 256) dch[e] = dones[tc * BB + e];
        __syncthreads();
        if (b < BB) for (int u = 0; u < 256; ++u) {
            int t = tc + u;
            if (t > 0 && prev > 0.5f) { ep++; start = t; }
            int pos = t - start;
            float d = dch[u * BB + b]; prev = d;
            int di = -1;
            if (ep < KK && pos < LMM) {
                int row = b * KK + ep, slot = row * LMM + pos;
                di = slot; g_dflag[slot] = d; g_mask[slot] = 1.f; g_cnt[row]++;
            }
            g_dst[t * BB + b] = di;
        }
        __syncthreads();
    }
}

/* ---- launch 1: Wc = W_sa@Wi fold + Wh4 transpose-pack ---- */
__global__ void prep_k(const float* __restrict__ Wsa, const float* __restrict__ bsa,
                       const float* __restrict__ Wi, const float* __restrict__ bi,
                       const float* __restrict__ Whh) {
    int idx = blockIdx.x * blockDim.x + threadIdx.x;
    if (idx < 193 * G3) {
        int a = idx / G3, j = idx % G3;
        const float* ar = (a < XW) ? (Wsa + a * HH) : bsa;
        float s = 0.f;
        for (int i = 0; i < HH; i++) s += ar[i] * Wi[i * G3 + j];
        if (a < XW) g_Wc[a * G3 + j] = s; else g_bc[j] = s + bi[j];
    } else {
        int w = idx - 193 * G3;
        if (w < 64 * G3) {
            int i4 = w / G3, col = w % G3;
            g_Wh4[w] = make_float4(Whh[(4 * i4 + 0) * G3 + col], Whh[(4 * i4 + 1) * G3 + col],
                                   Whh[(4 * i4 + 2) * G3 + col], Whh[(4 * i4 + 3) * G3 + col]);
        }
    }
}

/* ---- launch 2: fused se|ce embeddings (relu) ---- */
__global__ void sece_k(const float* __restrict__ ST, const float* __restrict__ AC,
                       const float* __restrict__ Wse, const float* __restrict__ bse,
                       const float* __restrict__ Wce, const float* __restrict__ bce) {
    __shared__ __align__(16) float xs[160 * 16];
    int n0 = blockIdx.x * 16, tid = threadIdx.x;
    for (int e = tid; e < 16 * 160; e += 192) {
        int r = e / 160, i = e % 160;
        xs[i * 16 + r] = (i < 128) ? ST[(size_t)(n0 + r) * 128 + i]
                                   : AC[(size_t)(n0 + r) * 32 + (i - 128)];
    }
    __syncthreads();
    const ulonglong2* X64 = (const ulonglong2*)xs;
    u64 acc[8];
    int se = (tid < 128);
    int j = se ? tid : (tid - 128);
    int IN = se ? 128 : 32, OUT = se ? 128 : 64, ioff = se ? 0 : 128;
    const float* W = se ? Wse : Wce;
    u64 bs = splat2(se ? bse[j] : bce[j]);
#pragma unroll
    for (int k = 0; k < 8; k++) acc[k] = bs;
    for (int i = 0; i < IN; i++) {
        int ii = ioff + i;
        ulonglong2 x0 = X64[ii * 4 + 0], x1 = X64[ii * 4 + 1];
        ulonglong2 x2 = X64[ii * 4 + 2], x3 = X64[ii * 4 + 3];
        u64 ws = splat2(W[i * OUT + j]);
        acc[0] = ffma2(x0.x, ws, acc[0]); acc[1] = ffma2(x0.y, ws, acc[1]);
        acc[2] = ffma2(x1.x, ws, acc[2]); acc[3] = ffma2(x1.y, ws, acc[3]);
        acc[4] = ffma2(x2.x, ws, acc[4]); acc[5] = ffma2(x2.y, ws, acc[5]);
        acc[6] = ffma2(x3.x, ws, acc[6]); acc[7] = ffma2(x3.y, ws, acc[7]);
    }
    int jo = se ? j : (128 + j);
#pragma unroll
    for (int k = 0; k < 8; k++) {
        float2 v = unpack2(acc[k]);
        g_xcat[(size_t)(n0 + 2 * k) * XW + jo] = fmaxf(v.x, 0.f);
        g_xcat[(size_t)(n0 + 2 * k + 1) * XW + jo] = fmaxf(v.y, 0.f);
    }
}

/* ---- launch 3: hid = [ce,ms]@W_h + b_h, scattered to episode layout ---- */
__global__ void hid_k(const float* __restrict__ MS, const float* __restrict__ W,
                      const float* __restrict__ B) {
    __shared__ __align__(16) float xs[96 * 16];
    int n0 = blockIdx.x * 16, tid = threadIdx.x;
    for (int e = tid; e < 16 * 96; e += 256) {
        int r = e / 96, i = e % 96;
        xs[i * 16 + r] = (i < 64) ? g_xcat[(size_t)(n0 + r) * XW + 128 + i]
                                  : MS[(size_t)(n0 + r) * 32 + (i - 64)];
    }
    __syncthreads();
    const ulonglong2* X64 = (const ulonglong2*)xs;
    int j = tid;
    u64 acc[8];
    u64 bs = splat2(B[j]);
#pragma unroll
    for (int k = 0; k < 8; k++) acc[k] = bs;
    for (int i = 0; i < 96; i++) {
        ulonglong2 x0 = X64[i * 4 + 0], x1 = X64[i * 4 + 1];
        ulonglong2 x2 = X64[i * 4 + 2], x3 = X64[i * 4 + 3];
        u64 ws = splat2(W[i * HH + j]);
        acc[0] = ffma2(x0.x, ws, acc[0]); acc[1] = ffma2(x0.y, ws, acc[1]);
        acc[2] = ffma2(x1.x, ws, acc[2]); acc[3] = ffma2(x1.y, ws, acc[3]);
        acc[4] = ffma2(x2.x, ws, acc[4]); acc[5] = ffma2(x2.y, ws, acc[5]);
        acc[6] = ffma2(x3.x, ws, acc[6]); acc[7] = ffma2(x3.y, ws, acc[7]);
    }
#pragma unroll
    for (int k = 0; k < 8; k++) {
        float2 v = unpack2(acc[k]);
        int da = g_dst[n0 + 2 * k];     if (da >= 0) g_hid[(size_t)da * HH + j] = v.x;
        int db = g_dst[n0 + 2 * k + 1]; if (db >= 0) g_hid[(size_t)db * HH + j] = v.y;
    }
}

/* ---- launch 4: gi GEMM, 64x128 tile, K=192.
   Thread (cg=tid&15, rg=tid>>4): rows rg*4..+3, cols {4cg..4cg+3} u {64+4cg..+3}.
   Bs row = 128 floats = 32 ulonglong2; b_lo=B64[k*32+cg], b_hi=B64[k*32+16+cg]. ---- */
#define AST 68
__global__ void __launch_bounds__(256, 1) gemm_k() {
    extern __shared__ float gs[];
    float* As = gs;                    /* [192][AST] transposed, 52224B */
    float* Bs = gs + 192 * AST;        /* [192][128], 98304B */
    int n0 = blockIdx.x * 64, j0 = blockIdx.y * 128, tid = threadIdx.x;
    int cg = tid & 15, rg = tid >> 4;
    const float4* Xc4 = (const float4*)g_xcat;
    const float4* Wc4 = (const float4*)g_Wc;
    for (int e = tid; e < 64 * 48; e += 256) {
        int r = e / 48, kq = e % 48;
        float4 x = Xc4[(size_t)(n0 + r) * 48 + kq];
        As[(4 * kq + 0) * AST + r] = x.x; As[(4 * kq + 1) * AST + r] = x.y;
        As[(4 * kq + 2) * AST + r] = x.z; As[(4 * kq + 3) * AST + r] = x.w;
    }
    float4* Bs4 = (float4*)Bs;
    for (int e = tid; e < 192 * 32; e += 256) {
        int k = e / 32, c4 = e % 32;
        Bs4[k * 32 + c4] = Wc4[(size_t)k * 192 + j0 / 4 + c4];
    }
    __syncthreads();
    u64 acc[4][4];
#pragma unroll
    for (int r = 0; r < 4; r++)
#pragma unroll
        for (int c = 0; c < 4; c++) acc[r][c] = 0ull;
    const ulonglong2* B64 = (const ulonglong2*)Bs;
#pragma unroll 4
    for (int k = 0; k < 192; k++) {
        float4 a = *(const float4*)(As + k * AST + rg * 4);
        ulonglong2 b_lo = B64[k * 32 + cg];        /* cols 4cg..4cg+3   */
        ulonglong2 b_hi = B64[k * 32 + 16 + cg];   /* cols 64+4cg..+3   */
        float av[4] = {a.x, a.y, a.z, a.w};
#pragma unroll
        for (int r = 0; r < 4; r++) {
            u64 s = splat2(av[r]);
            acc[r][0] = ffma2(s, b_lo.x, acc[r][0]);
            acc[r][1] = ffma2(s, b_lo.y, acc[r][1]);
            acc[r][2] = ffma2(s, b_hi.x, acc[r][2]);
            acc[r][3] = ffma2(s, b_hi.y, acc[r][3]);
        }
    }
    float4 blo = *(const float4*)(g_bc + j0 + cg * 4);
    float4 bhi = *(const float4*)(g_bc + j0 + 64 + cg * 4);
#pragma unroll
    for (int r = 0; r < 4; r++) {
        int dn = g_dst[n0 + rg * 4 + r];
        if (dn >= 0) {
            float2 v0 = unpack2(acc[r][0]), v1 = unpack2(acc[r][1]);
            float2 v2 = unpack2(acc[r][2]), v3 = unpack2(acc[r][3]);
            float* op = g_gi + (size_t)dn * G3 + j0;
            *(float4*)(op + cg * 4) =
                make_float4(v0.x + blo.x, v0.y + blo.y, v1.x + blo.z, v1.y + blo.w);
            *(float4*)(op + 64 + cg * 4) =
                make_float4(v2.x + bhi.x, v2.y + bhi.y, v3.x + bhi.z, v3.y + bhi.w);
        }
    }
}

/* ---- launch 5 (PROFILED): GRU recurrence ---- */
__global__ void __launch_bounds__(256, 1)
recur_k(const float* __restrict__ bh_, const float* __restrict__ Wout,
        const float* __restrict__ bout) {
    extern __shared__ float sm[];
    float4* whs4 = (float4*)sm;              /* 16*768 float4 = 196608B */
    float* hs = sm + 16 * G3 * 4;            /* [4][256] = 4096B */
    float* wos = hs + 1024;                  /* 256*17 = 17408B */
    float* bos = wos + 256 * 17;             /* 16 */
    int t = threadIdx.x, row0 = blockIdx.x * 4;
    for (int e = t; e < 16 * G3; e += 256) whs4[e] = g_Wh4[e];
    for (int e = t; e < 256 * 16; e += 256) { int j = e >> 4, a = e & 15; wos[j * 17 + a] = Wout[e]; }
    if (t < 16) bos[t] = bout[t];
    float bh0 = bh_[t], bh1 = bh_[t + 256], bh2 = bh_[t + 512];
    float h[4];
#pragma unroll
    for (int r = 0; r < 4; r++) h[r] = g_hid[(size_t)(row0 + r) * LMM * HH + t];
#pragma unroll
    for (int r = 0; r < 4; r++) hs[r * 256 + t] = h[r];
    int lr = t >> 6, sub = t & 63, la = sub >> 2, lq = sub & 3;
    const ulonglong2* ws64 = (const ulonglong2*)whs4;
    const ulonglong2* wg64 = (const ulonglong2*)g_Wh4;
    const ulonglong2* hp = (const ulonglong2*)hs;   /* row r at hp[r*64 + i4] */
    __syncthreads();

    for (int p = 0; p < LMM; p++) {
        int s0 = (row0 + 0) * LMM + p;
#pragma unroll
        for (int r = 0; r < 4; r++) {
            int sl = s0 + r * LMM;
            if (g_dflag[sl] > 0.5f) { h[r] = g_hid[(size_t)sl * HH + t]; hs[r * 256 + t] = h[r]; }
        }
        __syncthreads();
        float gi[4][3];
#pragma unroll
        for (int r = 0; r < 4; r++) {
            const float* gp = g_gi + (size_t)(s0 + r * LMM) * G3 + t;
            gi[r][0] = gp[0]; gi[r][1] = gp[256]; gi[r][2] = gp[512];
        }
        u64 aR[4] = {0, 0, 0, 0}, aZ[4] = {0, 0, 0, 0}, aN[4] = {0, 0, 0, 0};
#pragma unroll 4
        for (int i4 = 0; i4 < 16; i4++) {
            ulonglong2 w0 = ws64[i4 * G3 + t];
            ulonglong2 w1 = ws64[i4 * G3 + t + 256];
            ulonglong2 w2 = ws64[i4 * G3 + t + 512];
#pragma unroll
            for (int r = 0; r < 4; r++) {
                ulonglong2 hv = hp[r * 64 + i4];
                aR[r] = ffma2(hv.x, w0.x, aR[r]); aR[r] = ffma2(hv.y, w0.y, aR[r]);
                aZ[r] = ffma2(hv.x, w1.x, aZ[r]); aZ[r] = ffma2(hv.y, w1.y, aZ[r]);
                aN[r] = ffma2(hv.x, w2.x, aN[r]); aN[r] = ffma2(hv.y, w2.y, aN[r]);
            }
        }
#pragma unroll 4
        for (int i4 = 16; i4 < 64; i4++) {
            ulonglong2 w0 = wg64[i4 * G3 + t];
            ulonglong2 w1 = wg64[i4 * G3 + t + 256];
            ulonglong2 w2 = wg64[i4 * G3 + t + 512];
#pragma unroll
            for (int r = 0; r < 4; r++) {
                ulonglong2 hv = hp[r * 64 + i4];
                aR[r] = ffma2(hv.x, w0.x, aR[r]); aR[r] = ffma2(hv.y, w0.y, aR[r]);
                aZ[r] = ffma2(hv.x, w1.x, aZ[r]); aZ[r] = ffma2(hv.y, w1.y, aZ[r]);
                aN[r] = ffma2(hv.x, w2.x, aN[r]); aN[r] = ffma2(hv.y, w2.y, aN[r]);
            }
        }
        __syncthreads();
#pragma unroll
        for (int r = 0; r < 4; r++) {
            float2 fR = unpack2(aR[r]), fZ = unpack2(aZ[r]), fN = unpack2(aN[r]);
            float hr = fR.x + fR.y, hz = fZ.x + fZ.y, hn = fN.x + fN.y;
            float rg = 1.f / (1.f + expf(-(gi[r][0] + hr + bh0)));
            float zg = 1.f / (1.f + expf(-(gi[r][1] + hz + bh1)));
            float ng = tanhf(gi[r][2] + rg * (hn + bh2));
            h[r] = (1.f - zg) * ng + zg * h[r];
            hs[r * 256 + t] = h[r];
        }
        __syncthreads();
        float part = 0.f;
#pragma unroll 8
        for (int i = 0; i < 64; i++) {
            int iv = (i + lq * 8) & 63;
            int j = lq * 64 + iv;
            part += hs[lr * 256 + j] * wos[j * 17 + la];
        }
        part += __shfl_xor_sync(0xffffffffu, part, 1);
        part += __shfl_xor_sync(0xffffffffu, part, 2);
        if (lq == 0) {
            int slot = (row0 + lr) * LMM + p;
            g_logits[slot * AA + la] = (part + bos[la]) * g_mask[slot];
        }
        __syncthreads();
    }
}

/* ---- KL ---- */
__global__ void kl_k(const float* __restrict__ lm, const float* __restrict__ lv,
                     const float* __restrict__ lmt, const float* __restrict__ lvt) {
    __shared__ float red[256];
    int n = blockIdx.x * 256 + threadIdx.x;
    int t = n >> 5;
    int st = n * LD;
    float s = 0.f;
    const float* ms[2] = {lm, lmt};
    const float* vs[2] = {lv, lvt};
#pragma unroll
    for (int g = 0; g < 2; g++)
        for (int d = 0; d < LD; d++) {
            float mu = ms[g][st + d], logE = vs[g][st + d];
            float m = 0.f, logS = 0.f;
            if (t > 0) { m = ms[g][st - BB * LD + d]; logS = vs[g][st - BB * LD + d]; }
            float dd = m - mu;
            s += logS - logE + expf(logE - logS) + dd * dd * expf(-logS);
        }
    red[threadIdx.x] = 0.5f * (s - 64.f);
    __syncthreads();
    for (int o = 128; o; o >>= 1) {
        if (threadIdx.x < o) red[threadIdx.x] += red[threadIdx.x + o];
        __syncthreads();
    }
    if (threadIdx.x == 0) g_klp[blockIdx.x] = red[0];
}

__global__ void klf_k(float* out) {
    __shared__ float red[512];
    red[threadIdx.x] = g_klp[threadIdx.x];
    __syncthreads();
    for (int o = 256; o; o >>= 1) {
        if (threadIdx.x < o) red[threadIdx.x] += red[threadIdx.x + o];
        __syncthreads();
    }
    if (threadIdx.x == 0) out[0] = red[0];
}

__global__ void out_k(const int* __restrict__ pact, float* __restrict__ dout) {
    int l = blockIdx.x, b = threadIdx.x;
    float acc[16];
#pragma unroll
    for (int a = 0; a < 16; a++) acc[a] = 0.f;
    for (int k = 0; k < KK; k++) {
        int row = b * KK + k;
        int pp = l - (LMM - g_cnt[row]);
        if (pp >= 0) {
            const float* lp = g_logits + (row * LMM + pp) * AA;
#pragma unroll
            for (int a = 0; a < 16; a++) acc[a] += lp[a];
        }
    }
    float mx = acc[0];
#pragma unroll
    for (int a = 1; a < 16; a++) mx = fmaxf(mx, acc[a]);
    float se = 0.f;
#pragma unroll
    for (int a = 0; a < 16; a++) se += expf(acc[a] - mx);
    float lse = logf(se) + mx;
    int act = pact[l * BB + b];
    float lpv = acc[act] - lse;
    for (int o = 16; o; o >>= 1) lpv += __shfl_down_sync(0xffffffffu, lpv, o);
    if (b == 0) dout[1 + l] = lpv;
}

extern "C" void kernel_launch(void* const* d_in, const int* in_sizes, int n_in,
                              void* d_out, int out_size) {
    const float* state = (const float*)d_in[0];
    const float* lmean = (const float*)d_in[1];
    const float* llogv = (const float*)d_in[2];
    const float* lmeant = (const float*)d_in[3];
    const float* llogvt = (const float*)d_in[4];
    const float* achar = (const float*)d_in[5];
    const float* mstate = (const float*)d_in[6];
    const int*   pact   = (const int*)d_in[7];
    const float* dones  = (const float*)d_in[8];
    const float* Wse = (const float*)d_in[9];
    const float* bse = (const float*)d_in[10];
    const float* Wce = (const float*)d_in[11];
    const float* bce = (const float*)d_in[12];
    const float* Wsa = (const float*)d_in[13];
    const float* bsa = (const float*)d_in[14];
    const float* Wh  = (const float*)d_in[15];
    const float* bh  = (const float*)d_in[16];
    const float* Wi  = (const float*)d_in[17];
    const float* bi  = (const float*)d_in[18];
    const float* Whh = (const float*)d_in[19];
    const float* bhh = (const float*)d_in[20];
    const float* Wout = (const float*)d_in[21];
    const float* bout = (const float*)d_in[22];
    float* dout = (float*)d_out;

    static int attr_done = 0;
    size_t rsm = (size_t)16 * G3 * 16 + 4096 + 256 * 17 * 4 + 64;      /* 218176 */
    size_t gsm = (size_t)192 * AST * 4 + (size_t)192 * 128 * 4;        /* 150528 */
    if (!attr_done) {
        cudaFuncSetAttribute(recur_k, cudaFuncAttributeMaxDynamicSharedMemorySize, (int)rsm);
        cudaFuncSetAttribute(gemm_k, cudaFuncAttributeMaxDynamicSharedMemorySize, (int)gsm);
        attr_done = 1;
    }

    layoutinit_k<<<1, 256>>>(dones);                                     /* 0 */
    prep_k<<<(193 * G3 + 64 * G3 + 255) / 256, 256>>>(Wsa, bsa, Wi, bi, Whh); /* 1 */
    sece_k<<<NTB / 16, 192>>>(state, achar, Wse, bse, Wce, bce);         /* 2 */
    hid_k<<<NTB / 16, 256>>>(mstate, Wh, bh);                            /* 3 */
    gemm_k<<<dim3(NTB / 64, G3 / 128), 256, gsm>>>();                    /* 4 */
    recur_k<<<128, 256, rsm>>>(bhh, Wout, bout);                         /* 5 <- ncu */
    kl_k<<<512, 256>>>(lmean, llogv, lmeant, llogvt);                    /* 6 */
    klf_k<<<1, 512>>>(dout);                                             /* 7 */
    out_k<<<LMM, 32>>>(pact, dout);                                      /* 8 */
}